// round 12
// baseline (speedup 1.0000x reference)
#include <cuda_runtime.h>
#include <math.h>

#define S_DIM 512
#define B_DIM 32
#define T_DIM 1024
#define E_DIM 512
#define Q_DIM 128
#define SPB   16         // s-rows per block (= chunk)
#define NCH   (S_DIM / SPB)   // 32 chunks per batch
#define TCH   16         // staged t-chunk (rows in shared; 128B sw2 rows)
#define CUT   12.0f      // exponent cutoff: exp(-12) ~ 6e-6 (validated)
#define NTHR  256

// Scratch (allocation-free rule: __device__ globals).
__device__ float g_csum[B_DIM * NCH];   // chunk mean_raw totals
__device__ int   g_cflag[B_DIM * NCH];  // 0 -> 1 when chunk sum published

// Packed f32x2 helpers (Blackwell FFMA2 — only reachable via PTX).
static __device__ __forceinline__ unsigned long long pack2f(float a, float b) {
    unsigned long long r;
    asm("mov.b64 %0, {%1, %2};" : "=l"(r) : "f"(a), "f"(b));
    return r;
}
static __device__ __forceinline__ unsigned long long fma2(
    unsigned long long a, unsigned long long b, unsigned long long c) {
    unsigned long long d;
    asm("fma.rn.f32x2 %0, %1, %2, %3;" : "=l"(d) : "l"(a), "l"(b), "l"(c));
    return d;
}
static __device__ __forceinline__ int ld_acq(const int* p) {
    int v;
    asm volatile("ld.acquire.gpu.global.b32 %0, [%1];" : "=r"(v) : "l"(p) : "memory");
    return v;
}
static __device__ __forceinline__ void st_rel(int* p, int v) {
    asm volatile("st.release.gpu.global.b32 [%0], %1;" :: "l"(p), "r"(v) : "memory");
}
static __device__ __forceinline__ void cp_async16(unsigned smem_addr, const void* g) {
    asm volatile("cp.async.ca.shared.global [%0], [%1], 16;"
                 :: "r"(smem_addr), "l"(g) : "memory");
}
#define WRED(x) { _Pragma("unroll") \
    for (int _o = 16; _o; _o >>= 1) x += __shfl_xor_sync(0xFFFFFFFFu, x, _o); }

// ---------------------------------------------------------------------------
// ONE fused kernel, decoupled-lookback. Grid (B, NCH), 256 threads.
// Every block: own 16 dots -> chunk scan -> publish sum -> lookback-poll
// predecessors -> means -> windowed Gaussian context GEMM from shared.
// ---------------------------------------------------------------------------
__global__ void __launch_bounds__(NTHR, 4) ga_fused(
    const float* __restrict__ q,     // [S,B,Q]
    const float* __restrict__ emb,   // [T,B,E]
    const float* __restrict__ mask,  // [T,B]
    const float* __restrict__ pos,   // [S,B]
    const float* __restrict__ W,     // [2,Q]
    const float* __restrict__ bias,  // [2]
    float* __restrict__ out_ctx,     // [S,B,E]
    float* __restrict__ out_mean)    // [S,B]
{
    const int b    = blockIdx.x;
    const int c    = blockIdx.y;          // chunk id
    const int s0   = c * SPB;
    const int tid  = threadIdx.x;
    const int warp = tid >> 5;
    const int lane = tid & 31;
    const int half = tid >> 7;            // 0: si 0-7, 1: si 8-15
    const int h    = tid & 127;           // e-slot: floats [4h, 4h+4)

    __shared__ float tile[TCH * E_DIM];               // 32 KB staged rows
    __shared__ float p_mr[SPB];
    __shared__ float smean[SPB];
    __shared__ float sstd[SPB];
    __shared__ unsigned long long sw2[SPB][TCH];      // packed (w,w), 128B rows

    // ---- Phase 1: warp w computes dots for rows s0+2w, s0+2w+1 ----
    {
        float4 a0 = ((const float4*)W)[lane];
        float4 a1 = ((const float4*)W)[32 + lane];
        int s = s0 + 2 * warp;
        float4 x0 = ((const float4*)q)[((size_t)s * B_DIM + b) * 32 + lane];
        float4 x1 = ((const float4*)q)[((size_t)(s + 1) * B_DIM + b) * 32 + lane];
        float d00 = x0.x * a0.x + x0.y * a0.y + x0.z * a0.z + x0.w * a0.w;
        float d01 = x0.x * a1.x + x0.y * a1.y + x0.z * a1.z + x0.w * a1.w;
        float d10 = x1.x * a0.x + x1.y * a0.y + x1.z * a0.z + x1.w * a0.w;
        float d11 = x1.x * a1.x + x1.y * a1.y + x1.z * a1.z + x1.w * a1.w;
        WRED(d00); WRED(d01); WRED(d10); WRED(d11);
        float b0 = bias[0], b1 = bias[1];
        if (lane == 0) {
            p_mr[2 * warp]     = __expf(d00 + b0);
            sstd[2 * warp]     = __expf(d01 + b1);
            p_mr[2 * warp + 1] = __expf(d10 + b0);
            sstd[2 * warp + 1] = __expf(d11 + b1);
        }
    }
    __syncthreads();

    // ---- Phase 2+3: warp 0 — scan, publish, lookback, means ----
    if (warp == 0) {
        float mr = (lane < SPB) ? p_mr[lane] : 0.0f;
        #pragma unroll
        for (int off = 1; off < SPB; off <<= 1) {
            float y = __shfl_up_sync(0xFFFFFFFFu, mr, off);
            if (lane >= off) mr += y;
        }
        float total = __shfl_sync(0xFFFFFFFFu, mr, SPB - 1);
        if (lane == 0) {
            g_csum[b * NCH + c] = total;
            st_rel(&g_cflag[b * NCH + c], 1);   // release orders the store above
        }
        // Lookback: lane p polls predecessor chunk p (p < c).
        float prev = 0.0f;
        if (lane < c) {
            while (!ld_acq(&g_cflag[b * NCH + lane])) __nanosleep(32);
            prev = g_csum[b * NCH + lane];
        }
        WRED(prev);
        if (lane < SPB) {
            int s = s0 + lane;
            float mean = pos[(size_t)s * B_DIM + b] + (prev + mr) * 0.05f;
            smean[lane] = mean;
            out_mean[(size_t)s * B_DIM + b] = mean;
        }
    }
    __syncthreads();

    // ---- Phase 4: union window (warp-parallel, uniform result) ----
    int tlo, thi;
    {
        int si = lane & 15;
        float mean = smean[si];
        float hw   = sqrtf(CUT / sstd[si]);
        int lo = (int)fmaxf(0.0f, ceilf(mean - hw));
        int hi = (int)fminf((float)(T_DIM - 1), floorf(mean + hw));
        #pragma unroll
        for (int off = 8; off; off >>= 1) {
            lo = min(lo, __shfl_xor_sync(0xFFFFFFFFu, lo, off));
            hi = max(hi, __shfl_xor_sync(0xFFFFFFFFu, hi, off));
        }
        tlo = lo; thi = hi;
    }

    ulonglong2 acc[8];
    #pragma unroll
    for (int i = 0; i < 8; i++) { acc[i].x = acc[i].y = 0ull; }

    const unsigned tile_base = (unsigned)__cvta_generic_to_shared(tile);

    for (int tb = tlo; tb <= thi; tb += TCH) {
        int n  = min(TCH, thi - tb + 1);
        int n2 = (n + 1) & ~1;            // even row count for the pair loop
        __syncthreads();   // protect tile + sw2 reuse across chunks

        // Stage n2 rows (2 KB each): threads split row-pairs, 16B cp.async.
        // Row index clamped to T_DIM-1 (pad rows get weight 0; data finite).
        for (int j = half; j < n2; j += 2) {
            int t = min(tb + j, T_DIM - 1);
            const float* src = emb + ((size_t)t * B_DIM + b) * E_DIM + h * 4;
            cp_async16(tile_base + (unsigned)(j * E_DIM + h * 4) * 4u, src);
        }
        asm volatile("cp.async.commit_group;" ::: "memory");

        // Weights (overlap the copies): 256 threads fill 16x16 slots.
        {
            int si = tid >> 4;                // 0..15
            int tj = tid & (TCH - 1);
            float wv = 0.0f;
            if (tj < n) {
                int   t = tb + tj;
                float d = smean[si] - (float)t;
                wv = __expf(-sstd[si] * d * d) * mask[(size_t)t * B_DIM + b];
            }
            sw2[si][tj] = pack2f(wv, wv);
        }

        asm volatile("cp.async.wait_group 0;" ::: "memory");
        __syncthreads();

        // Pair-row FMA from shared: per 2 rows, 2 LDS.128 (v0,v1) +
        // 8 LDS.128 (weight pairs) + 32 FFMA2.
        #pragma unroll 4
        for (int j = 0; j < n2; j += 2) {
            ulonglong2 v0 = *(const ulonglong2*)&tile[j * E_DIM + h * 4];
            ulonglong2 v1 = *(const ulonglong2*)&tile[(j + 1) * E_DIM + h * 4];
            #pragma unroll
            for (int r = 0; r < 8; r++) {
                ulonglong2 wp = *(const ulonglong2*)&sw2[half * 8 + r][j];
                acc[r].x = fma2(v0.x, wp.x, acc[r].x);
                acc[r].y = fma2(v0.y, wp.x, acc[r].y);
                acc[r].x = fma2(v1.x, wp.y, acc[r].x);
                acc[r].y = fma2(v1.y, wp.y, acc[r].y);
            }
        }
    }

    float* op = out_ctx + ((size_t)(s0 + half * 8) * B_DIM + b) * E_DIM + h * 4;
    #pragma unroll
    for (int r = 0; r < 8; r++) {
        *(ulonglong2*)op = acc[r];
        op += (size_t)B_DIM * E_DIM;
    }
}

// ---------------------------------------------------------------------------
extern "C" void kernel_launch(void* const* d_in, const int* in_sizes, int n_in,
                              void* d_out, int out_size) {
    const float* query = (const float*)d_in[0];  // [S,B,Q]
    const float* emb   = (const float*)d_in[1];  // [T,B,E]
    const float* mask  = (const float*)d_in[2];  // [T,B]
    const float* pos   = (const float*)d_in[3];  // [S,B]
    const float* W     = (const float*)d_in[4];  // [2,Q]
    const float* bias  = (const float*)d_in[5];  // [2]

    float* out_ctx  = (float*)d_out;                                  // [S,B,E]
    float* out_mean = (float*)d_out + (size_t)S_DIM * B_DIM * E_DIM;  // [S,B]

    dim3 grid(B_DIM, NCH);   // 1024 blocks, no dedicated producers
    ga_fused<<<grid, NTHR>>>(query, emb, mask, pos, W, bias, out_ctx, out_mean);
}